// round 2
// baseline (speedup 1.0000x reference)
#include <cuda_runtime.h>
#include <math.h>

#define NB 8
#define NH 16
#define ND 1024
#define NHD 64
#define NPAST 8192
#define NBH (NB*NH)                 // 128
#define KEYS_PER_WARP 32
#define NCHUNK (NPAST/KEYS_PER_WARP) // 256 warp-chunks per (b,h)
#define GRIDX (NCHUNK/8)             // 32 blocks of 8 warps

// Scratch (allocation-free: __device__ globals)
__device__ float g_qkv[3*NB*ND];          // q | k_new | v_new, roped in place
__device__ float g_m[NBH*NCHUNK];
__device__ float g_l[NBH*NCHUNK];
__device__ float g_acc[NBH*NCHUNK*NHD];   // 8 MB
__device__ float g_ctx[NB*ND];

// ---------------------------------------------------------------------------
// Kernel A: QKV projection.  grid (384, NB), 256 thr.  Warp w computes output
// row r = bx*8+w of [Wq;Wk;Wv] for batch by.  x row staged in smem.
// ---------------------------------------------------------------------------
__global__ void proj_kernel(const float* __restrict__ x,
                            const float* __restrict__ Wq, const float* __restrict__ bq,
                            const float* __restrict__ Wk, const float* __restrict__ bk,
                            const float* __restrict__ Wv, const float* __restrict__ bv) {
    __shared__ float xs[ND];
    const int b = blockIdx.y;
    for (int i = threadIdx.x; i < ND; i += blockDim.x) xs[i] = x[b*ND + i];
    __syncthreads();

    const int warp = threadIdx.x >> 5, lane = threadIdx.x & 31;
    const int r = blockIdx.x * 8 + warp;           // 0..3071
    const int which = r >> 10;                     // 0=q 1=k 2=v
    const int row = r & 1023;
    const float* W; const float* bias;
    if (which == 0)      { W = Wq; bias = bq; }
    else if (which == 1) { W = Wk; bias = bk; }
    else                 { W = Wv; bias = bv; }

    const float4* Wr  = (const float4*)(W + (size_t)row * ND);
    const float4* xs4 = (const float4*)xs;
    float acc = 0.f;
#pragma unroll
    for (int it = 0; it < ND/128; ++it) {
        float4 w4 = Wr[it*32 + lane];
        float4 x4 = xs4[it*32 + lane];
        acc += w4.x*x4.x + w4.y*x4.y + w4.z*x4.z + w4.w*x4.w;
    }
#pragma unroll
    for (int o = 16; o; o >>= 1) acc += __shfl_xor_sync(0xffffffffu, acc, o);
    if (lane == 0) g_qkv[which*NB*ND + b*ND + row] = acc + bias[row];
}

// ---------------------------------------------------------------------------
// Kernel B: RoPE (rotate-half, base 10000, pos = NPAST) applied in place to
// q and k_new.  One thread per (bh, freq-pair).  4096 threads total.
// ---------------------------------------------------------------------------
__global__ void rope_kernel() {
    const int t = blockIdx.x * blockDim.x + threadIdx.x;
    if (t >= NBH*32) return;
    const int bh = t >> 5;
    const int i  = t & 31;                          // freq index 0..31
    const int b = bh / NH, h = bh % NH;

    const float inv = expf(-((float)(2*i) / (float)NHD) * logf(10000.f));
    const float ang = (float)NPAST * inv;
    float s, c; sincosf(ang, &s, &c);

    const int base = b*ND + h*NHD;
    float* q = g_qkv + base;
    float q1 = q[i], q2 = q[i+32];
    q[i]    = q1*c - q2*s;
    q[i+32] = q2*c + q1*s;

    float* k = g_qkv + NB*ND + base;
    float k1 = k[i], k2 = k[i+32];
    k[i]    = k1*c - k2*s;
    k[i+32] = k2*c + k1*s;
}

// ---------------------------------------------------------------------------
// Kernel C: flash-decoding partials over the past KV.  grid (GRIDX, NBH),
// 256 thr (8 warps).  Warp-per-key online softmax: lane l holds dims
// {2l, 2l+1}; each key = one coalesced 256B K row + 256B V row.
// ---------------------------------------------------------------------------
__global__ void attn_partial(const float* __restrict__ past_k,
                             const float* __restrict__ past_v) {
    const int bh   = blockIdx.y;
    const int warp = threadIdx.x >> 5, lane = threadIdx.x & 31;
    const int chunk = blockIdx.x * 8 + warp;       // 0..255
    const int b = bh >> 4, h = bh & 15;

    const float2 q2 = ((const float2*)(g_qkv + b*ND + h*NHD))[lane];

    const size_t koff = ((size_t)bh * NPAST + (size_t)chunk * KEYS_PER_WARP) * NHD;
    const float2* kbase = (const float2*)(past_k + koff);
    const float2* vbase = (const float2*)(past_v + koff);

    float m = -1e30f, l = 0.f;
    float2 acc = make_float2(0.f, 0.f);

#pragma unroll 4
    for (int j = 0; j < KEYS_PER_WARP; ++j) {
        float2 k2 = kbase[j*32 + lane];
        float2 v2 = vbase[j*32 + lane];
        float s = q2.x*k2.x + q2.y*k2.y;
#pragma unroll
        for (int o = 16; o; o >>= 1) s += __shfl_xor_sync(0xffffffffu, s, o);
        s *= 0.125f;                               // 1/sqrt(64)
        float nm = fmaxf(m, s);
        float f  = __expf(m - nm);
        float p  = __expf(s - nm);
        acc.x = acc.x*f + p*v2.x;
        acc.y = acc.y*f + p*v2.y;
        l = l*f + p;
        m = nm;
    }

    const int idx = bh*NCHUNK + chunk;
    ((float2*)(g_acc + (size_t)idx*NHD))[lane] = acc;
    if (lane == 0) { g_m[idx] = m; g_l[idx] = l; }
}

// ---------------------------------------------------------------------------
// Kernel D: combine partials + fold in the freshly-projected key/value.
// grid NBH, 64 threads (thread d owns output dim d).
// ---------------------------------------------------------------------------
__global__ void attn_reduce() {
    const int bh = blockIdx.x;
    const int d  = threadIdx.x;
    const int b = bh >> 4, h = bh & 15;

    const float* mptr = g_m + bh*NCHUNK;
    const float* lptr = g_l + bh*NCHUNK;
    const float* aptr = g_acc + (size_t)bh*NCHUNK*NHD;

    float M = -1e30f;
    for (int i = 0; i < NCHUNK; ++i) M = fmaxf(M, mptr[i]);

    float L = 0.f, a = 0.f;
    for (int i = 0; i < NCHUNK; ++i) {
        float w = __expf(mptr[i] - M);
        L += lptr[i] * w;
        a += aptr[i*NHD + d] * w;
    }

    // new key at position NPAST
    __shared__ float red[NHD];
    const float qd = g_qkv[b*ND + h*NHD + d];
    const float kd = g_qkv[NB*ND + b*ND + h*NHD + d];
    red[d] = qd * kd;
    __syncthreads();
#pragma unroll
    for (int o = 32; o > 0; o >>= 1) {
        if (d < o) red[d] += red[d + o];
        __syncthreads();
    }
    const float s_new = red[0] * 0.125f;

    const float M2 = fmaxf(M, s_new);
    const float w0 = __expf(M - M2);
    const float p  = __expf(s_new - M2);
    const float vd = g_qkv[2*NB*ND + b*ND + h*NHD + d];
    a = a*w0 + p*vd;
    L = L*w0 + p;

    g_ctx[b*ND + h*NHD + d] = a / L;
}

// ---------------------------------------------------------------------------
// Kernel E: output projection ctx @ Wo.T + bo.  grid (128, NB), 256 thr.
// ---------------------------------------------------------------------------
__global__ void outproj_kernel(const float* __restrict__ Wo,
                               const float* __restrict__ bo,
                               float* __restrict__ out) {
    __shared__ float cs[ND];
    const int b = blockIdx.y;
    for (int i = threadIdx.x; i < ND; i += blockDim.x) cs[i] = g_ctx[b*ND + i];
    __syncthreads();

    const int warp = threadIdx.x >> 5, lane = threadIdx.x & 31;
    const int r = blockIdx.x * 8 + warp;           // 0..1023
    const float4* Wr  = (const float4*)(Wo + (size_t)r * ND);
    const float4* cs4 = (const float4*)cs;
    float acc = 0.f;
#pragma unroll
    for (int it = 0; it < ND/128; ++it) {
        float4 w4 = Wr[it*32 + lane];
        float4 c4 = cs4[it*32 + lane];
        acc += w4.x*c4.x + w4.y*c4.y + w4.z*c4.z + w4.w*c4.w;
    }
#pragma unroll
    for (int o = 16; o; o >>= 1) acc += __shfl_xor_sync(0xffffffffu, acc, o);
    if (lane == 0) out[b*ND + r] = acc + bo[r];
}

// ---------------------------------------------------------------------------
extern "C" void kernel_launch(void* const* d_in, const int* in_sizes, int n_in,
                              void* d_out, int out_size) {
    const float* x      = (const float*)d_in[0];
    const float* Wq     = (const float*)d_in[1];
    const float* bq     = (const float*)d_in[2];
    const float* Wk     = (const float*)d_in[3];
    const float* bk     = (const float*)d_in[4];
    const float* Wv     = (const float*)d_in[5];
    const float* bv     = (const float*)d_in[6];
    const float* Wo     = (const float*)d_in[7];
    const float* bo     = (const float*)d_in[8];
    const float* past_k = (const float*)d_in[9];
    const float* past_v = (const float*)d_in[10];
    float* out = (float*)d_out;

    proj_kernel<<<dim3(3*ND/8, NB), 256>>>(x, Wq, bq, Wk, bk, Wv, bv);
    rope_kernel<<<(NBH*32 + 255)/256, 256>>>();
    attn_partial<<<dim3(GRIDX, NBH), 256>>>(past_k, past_v);
    attn_reduce<<<NBH, NHD>>>();
    outproj_kernel<<<dim3(ND/8, NB), 256>>>(Wo, bo, out);
}

// round 3
// speedup vs baseline: 1.3571x; 1.3571x over previous
#include <cuda_runtime.h>
#include <math.h>

#define NB 8
#define NH 16
#define ND 1024
#define NHD 64
#define NPAST 8192
#define NBH (NB*NH)                   // 128
#define KEYS_PER_WARP 32
#define WARPS_PB 8
#define KEYS_PB (KEYS_PER_WARP*WARPS_PB)  // 256 keys per block
#define NCHUNK (NPAST/KEYS_PB)            // 32 block-chunks per (b,h)
#define LN10000 9.210340371976184f

// Scratch (allocation-free: __device__ globals)
__device__ float g_qkv[3*NB*ND];            // q | k_new | v_new (pre-rope)
__device__ float g_m[NBH*NCHUNK];
__device__ float g_l[NBH*NCHUNK];
__device__ float g_acc[NBH*NCHUNK*NHD];     // 1 MB
__device__ float g_ctx[NB*ND];

// ---------------------------------------------------------------------------
// Kernel A: QKV projection.  grid (384, NB), 256 thr.  Warp w computes output
// row r = bx*8+w of [Wq;Wk;Wv] for batch by.  x row staged in smem.
// ---------------------------------------------------------------------------
__global__ void proj_kernel(const float* __restrict__ x,
                            const float* __restrict__ Wq, const float* __restrict__ bq,
                            const float* __restrict__ Wk, const float* __restrict__ bk,
                            const float* __restrict__ Wv, const float* __restrict__ bv) {
    __shared__ float xs[ND];
    const int b = blockIdx.y;
    for (int i = threadIdx.x; i < ND; i += blockDim.x) xs[i] = x[b*ND + i];
    __syncthreads();

    const int warp = threadIdx.x >> 5, lane = threadIdx.x & 31;
    const int r = blockIdx.x * 8 + warp;           // 0..3071
    const int which = r >> 10;                     // 0=q 1=k 2=v
    const int row = r & 1023;
    const float* W; const float* bias;
    if (which == 0)      { W = Wq; bias = bq; }
    else if (which == 1) { W = Wk; bias = bk; }
    else                 { W = Wv; bias = bv; }

    const float4* Wr  = (const float4*)(W + (size_t)row * ND);
    const float4* xs4 = (const float4*)xs;
    float acc = 0.f;
#pragma unroll
    for (int it = 0; it < ND/128; ++it) {
        float4 w4 = Wr[it*32 + lane];
        float4 x4 = xs4[it*32 + lane];
        acc += w4.x*x4.x + w4.y*x4.y + w4.z*x4.z + w4.w*x4.w;
    }
#pragma unroll
    for (int o = 16; o; o >>= 1) acc += __shfl_xor_sync(0xffffffffu, acc, o);
    if (lane == 0) g_qkv[which*NB*ND + b*ND + row] = acc + bias[row];
}

// ---------------------------------------------------------------------------
// Kernel B: flash-decoding partials.  grid (NCHUNK, NBH), 256 thr (8 warps).
// RoPE(q) fused in the prologue.  Warp-per-key online softmax over 32 keys;
// the block combines its 8 warp partials in smem -> ONE partial per block.
// ---------------------------------------------------------------------------
__global__ void attn_partial(const float* __restrict__ past_k,
                             const float* __restrict__ past_v) {
    const int bh   = blockIdx.y;
    const int warp = threadIdx.x >> 5, lane = threadIdx.x & 31;
    const int b = bh >> 4, h = bh & 15;

    __shared__ float qs[NHD];
    __shared__ float sm_m[WARPS_PB], sm_l[WARPS_PB];
    __shared__ float sm_acc[WARPS_PB][NHD];

    if (threadIdx.x < 32) {
        const int i = threadIdx.x;                 // freq index 0..31
        const float inv = __expf(-((float)(2*i) / (float)NHD) * LN10000);
        float sn, cs; __sincosf((float)NPAST * inv, &sn, &cs);
        const float* gq = g_qkv + b*ND + h*NHD;
        const float q1 = gq[i], q2 = gq[i+32];
        qs[i]    = q1*cs - q2*sn;
        qs[i+32] = q2*cs + q1*sn;
    }
    __syncthreads();

    const float2 q2 = ((const float2*)qs)[lane];

    const int wchunk = blockIdx.x * WARPS_PB + warp;   // 0..255
    const size_t koff = ((size_t)bh * NPAST + (size_t)wchunk * KEYS_PER_WARP) * NHD;
    const float2* kbase = (const float2*)(past_k + koff);
    const float2* vbase = (const float2*)(past_v + koff);

    float m = -1e30f, l = 0.f;
    float2 acc = make_float2(0.f, 0.f);

#pragma unroll 4
    for (int j = 0; j < KEYS_PER_WARP; ++j) {
        float2 k2 = __ldcs(kbase + j*32 + lane);
        float2 v2 = __ldcs(vbase + j*32 + lane);
        float s = q2.x*k2.x + q2.y*k2.y;
#pragma unroll
        for (int o = 16; o; o >>= 1) s += __shfl_xor_sync(0xffffffffu, s, o);
        s *= 0.125f;                               // 1/sqrt(64)
        float nm = fmaxf(m, s);
        float f  = __expf(m - nm);
        float p  = __expf(s - nm);
        acc.x = acc.x*f + p*v2.x;
        acc.y = acc.y*f + p*v2.y;
        l = l*f + p;
        m = nm;
    }

    ((float2*)sm_acc[warp])[lane] = acc;
    if (lane == 0) { sm_m[warp] = m; sm_l[warp] = l; }
    __syncthreads();

    // First 64 threads combine the 8 warp partials -> one block partial.
    if (threadIdx.x < NHD) {
        const int d = threadIdx.x;
        float M = sm_m[0];
#pragma unroll
        for (int w = 1; w < WARPS_PB; ++w) M = fmaxf(M, sm_m[w]);
        float L = 0.f, a = 0.f;
#pragma unroll
        for (int w = 0; w < WARPS_PB; ++w) {
            const float wg = __expf(sm_m[w] - M);
            a += sm_acc[w][d] * wg;
            L += sm_l[w] * wg;
        }
        const int idx = bh*NCHUNK + blockIdx.x;
        g_acc[idx*NHD + d] = a;
        if (d == 0) { g_m[idx] = M; g_l[idx] = L; }
    }
}

// ---------------------------------------------------------------------------
// Kernel C: combine 32 block partials per (b,h) + fold in the new key/value
// (RoPE(k_new) fused).  grid NBH, 256 thr: c = tid>>6 handles chunks c,c+4,...
// ---------------------------------------------------------------------------
__global__ void attn_reduce() {
    const int bh  = blockIdx.x;
    const int tid = threadIdx.x;
    const int c = tid >> 6, d = tid & 63;
    const int b = bh >> 4, h = bh & 15;

    __shared__ float qs[NHD], ks[NHD];
    __shared__ float s_acc[4][NHD];
    __shared__ float s_l[4];
    __shared__ float red[NHD];
    __shared__ float s_dot;

    if (tid < 32) {
        const int i = tid;
        const float inv = __expf(-((float)(2*i) / (float)NHD) * LN10000);
        float sn, cs; __sincosf((float)NPAST * inv, &sn, &cs);
        const float* gq = g_qkv + b*ND + h*NHD;
        const float* gk = g_qkv + NB*ND + b*ND + h*NHD;
        const float q1 = gq[i], q2 = gq[i+32];
        qs[i]    = q1*cs - q2*sn;
        qs[i+32] = q2*cs + q1*sn;
        const float k1 = gk[i], k2 = gk[i+32];
        ks[i]    = k1*cs - k2*sn;
        ks[i+32] = k2*cs + k1*sn;
    }
    __syncthreads();

    const float* mptr = g_m + bh*NCHUNK;
    const float* lptr = g_l + bh*NCHUNK;
    const float* aptr = g_acc + (size_t)bh*NCHUNK*NHD;

    float M = -1e30f;
#pragma unroll
    for (int i = 0; i < NCHUNK; ++i) M = fmaxf(M, mptr[i]);

    float L = 0.f, a = 0.f;
#pragma unroll
    for (int i = c; i < NCHUNK; i += 4) {
        const float w = __expf(mptr[i] - M);
        L += lptr[i] * w;
        a += aptr[i*NHD + d] * w;
    }
    s_acc[c][d] = a;
    if (d == 0) s_l[c] = L;

    if (tid < NHD) red[tid] = qs[tid] * ks[tid];
    __syncthreads();

    if (tid < 32) {
        float v = red[tid] + red[tid + 32];
#pragma unroll
        for (int o = 16; o; o >>= 1) v += __shfl_xor_sync(0xffffffffu, v, o);
        if (tid == 0) s_dot = v * 0.125f;          // score of the new key
    }
    __syncthreads();

    if (tid < NHD) {
        float A  = s_acc[0][d] + s_acc[1][d] + s_acc[2][d] + s_acc[3][d];
        float Lt = s_l[0] + s_l[1] + s_l[2] + s_l[3];
        const float s_new = s_dot;
        const float M2 = fmaxf(M, s_new);
        const float w0 = __expf(M - M2);
        const float p  = __expf(s_new - M2);
        const float vd = g_qkv[2*NB*ND + b*ND + h*NHD + d];
        A  = A*w0 + p*vd;
        Lt = Lt*w0 + p;
        g_ctx[b*ND + h*NHD + d] = A / Lt;
    }
}

// ---------------------------------------------------------------------------
// Kernel D: output projection ctx @ Wo.T + bo.  grid (128, NB), 256 thr.
// ---------------------------------------------------------------------------
__global__ void outproj_kernel(const float* __restrict__ Wo,
                               const float* __restrict__ bo,
                               float* __restrict__ out) {
    __shared__ float cs[ND];
    const int b = blockIdx.y;
    for (int i = threadIdx.x; i < ND; i += blockDim.x) cs[i] = g_ctx[b*ND + i];
    __syncthreads();

    const int warp = threadIdx.x >> 5, lane = threadIdx.x & 31;
    const int r = blockIdx.x * 8 + warp;           // 0..1023
    const float4* Wr  = (const float4*)(Wo + (size_t)r * ND);
    const float4* cs4 = (const float4*)cs;
    float acc = 0.f;
#pragma unroll
    for (int it = 0; it < ND/128; ++it) {
        float4 w4 = Wr[it*32 + lane];
        float4 c4 = cs4[it*32 + lane];
        acc += w4.x*c4.x + w4.y*c4.y + w4.z*c4.z + w4.w*c4.w;
    }
#pragma unroll
    for (int o = 16; o; o >>= 1) acc += __shfl_xor_sync(0xffffffffu, acc, o);
    if (lane == 0) out[b*ND + r] = acc + bo[r];
}

// ---------------------------------------------------------------------------
extern "C" void kernel_launch(void* const* d_in, const int* in_sizes, int n_in,
                              void* d_out, int out_size) {
    const float* x      = (const float*)d_in[0];
    const float* Wq     = (const float*)d_in[1];
    const float* bq     = (const float*)d_in[2];
    const float* Wk     = (const float*)d_in[3];
    const float* bk     = (const float*)d_in[4];
    const float* Wv     = (const float*)d_in[5];
    const float* bv     = (const float*)d_in[6];
    const float* Wo     = (const float*)d_in[7];
    const float* bo     = (const float*)d_in[8];
    const float* past_k = (const float*)d_in[9];
    const float* past_v = (const float*)d_in[10];
    float* out = (float*)d_out;

    proj_kernel<<<dim3(3*ND/8, NB), 256>>>(x, Wq, bq, Wk, bk, Wv, bv);
    attn_partial<<<dim3(NCHUNK, NBH), 256>>>(past_k, past_v);
    attn_reduce<<<NBH, 256>>>();
    outproj_kernel<<<dim3(ND/8, NB), 256>>>(Wo, bo, out);
}

// round 4
// speedup vs baseline: 1.4415x; 1.0622x over previous
#include <cuda_runtime.h>
#include <math.h>

#define NB 8
#define NH 16
#define ND 1024
#define NHD 64
#define NPAST 8192
#define NBH (NB*NH)                   // 128
#define KEYS_PER_WARP 32
#define WARPS_PB 8
#define KEYS_PB (KEYS_PER_WARP*WARPS_PB)  // 256 keys per block
#define NCHUNK (NPAST/KEYS_PB)            // 32 block-chunks per (b,h)
#define LN10000 9.210340371976184f

// Scratch (allocation-free: __device__ globals)
__device__ float g_qkv[3*NB*ND];            // q | k_new | v_new (pre-rope)
__device__ float g_m[NBH*NCHUNK];
__device__ float g_l[NBH*NCHUNK];
__device__ float g_acc[NBH*NCHUNK*NHD];     // 1 MB
__device__ float g_ctx[NB*ND];

// ---------------------------------------------------------------------------
// Kernel A: QKV projection, batch-amortized.  grid 384, 256 thr.
// All 8 batch x-vectors staged in smem; warp w computes row r = bx*8+w of
// [Wq;Wk;Wv] for ALL batches (weight row read once, 8 indep accumulators).
// ---------------------------------------------------------------------------
__global__ void proj_kernel(const float* __restrict__ x,
                            const float* __restrict__ Wq, const float* __restrict__ bq,
                            const float* __restrict__ Wk, const float* __restrict__ bk,
                            const float* __restrict__ Wv, const float* __restrict__ bv) {
    __shared__ float xs[NB*ND];                     // 32 KB
    for (int i = threadIdx.x; i < NB*ND; i += blockDim.x) xs[i] = x[i];
    __syncthreads();

    const int warp = threadIdx.x >> 5, lane = threadIdx.x & 31;
    const int r = blockIdx.x * 8 + warp;            // 0..3071
    const int which = r >> 10;                      // 0=q 1=k 2=v
    const int row = r & 1023;
    const float* W; const float* bias;
    if (which == 0)      { W = Wq; bias = bq; }
    else if (which == 1) { W = Wk; bias = bk; }
    else                 { W = Wv; bias = bv; }

    const float4* Wr  = (const float4*)(W + (size_t)row * ND);
    const float4* xs4 = (const float4*)xs;          // [NB][256]
    float acc[NB];
#pragma unroll
    for (int b = 0; b < NB; ++b) acc[b] = 0.f;

#pragma unroll
    for (int it = 0; it < ND/128; ++it) {
        const float4 w4 = Wr[it*32 + lane];
#pragma unroll
        for (int b = 0; b < NB; ++b) {
            const float4 x4 = xs4[b*(ND/4) + it*32 + lane];
            acc[b] += w4.x*x4.x + w4.y*x4.y + w4.z*x4.z + w4.w*x4.w;
        }
    }
#pragma unroll
    for (int b = 0; b < NB; ++b) {
#pragma unroll
        for (int o = 16; o; o >>= 1) acc[b] += __shfl_xor_sync(0xffffffffu, acc[b], o);
    }
    if (lane == 0) {
        const float bv_ = bias[row];
#pragma unroll
        for (int b = 0; b < NB; ++b)
            g_qkv[which*NB*ND + b*ND + row] = acc[b] + bv_;
    }
}

// ---------------------------------------------------------------------------
// Kernel B: flash-decoding partials.  grid (NCHUNK, NBH), 256 thr (8 warps).
// RoPE(q) fused.  float4 loads: lanes 0-15 own key 2j, lanes 16-31 key 2j+1.
// Dot reduce = 4 shuffles per 2 keys; softmax state replicated per half-warp.
// ---------------------------------------------------------------------------
__global__ void attn_partial(const float* __restrict__ past_k,
                             const float* __restrict__ past_v) {
    const int bh   = blockIdx.y;
    const int warp = threadIdx.x >> 5, lane = threadIdx.x & 31;
    const int b = bh >> 4, h = bh & 15;

    __shared__ float qs[NHD];
    __shared__ float sm_m[WARPS_PB], sm_l[WARPS_PB];
    __shared__ float sm_acc[WARPS_PB][NHD];

    if (threadIdx.x < 32) {
        const int i = threadIdx.x;                  // freq index 0..31
        const float inv = expf(-((float)(2*i) / (float)NHD) * LN10000);
        float sn, cs; sincosf((float)NPAST * inv, &sn, &cs);
        const float* gq = g_qkv + b*ND + h*NHD;
        const float q1 = gq[i], q2 = gq[i+32];
        qs[i]    = q1*cs - q2*sn;
        qs[i+32] = q2*cs + q1*sn;
    }
    __syncthreads();

    const int l16 = lane & 15;
    const float4 q4 = ((const float4*)qs)[l16];

    const int wchunk = blockIdx.x * WARPS_PB + warp;   // 0..255
    const size_t off = ((size_t)bh * NPAST + (size_t)wchunk * KEYS_PER_WARP) * NHD;
    const float4* kb = (const float4*)(past_k + off);
    const float4* vb = (const float4*)(past_v + off);

    float m = -1e30f, l = 0.f;
    float4 acc = make_float4(0.f, 0.f, 0.f, 0.f);

#pragma unroll 4
    for (int j = 0; j < KEYS_PER_WARP/2; ++j) {
        const float4 k4 = __ldcs(kb + j*32 + lane);    // 2 key rows / warp
        const float4 v4 = __ldcs(vb + j*32 + lane);
        float s = q4.x*k4.x + q4.y*k4.y + q4.z*k4.z + q4.w*k4.w;
        s += __shfl_xor_sync(0xffffffffu, s, 1);
        s += __shfl_xor_sync(0xffffffffu, s, 2);
        s += __shfl_xor_sync(0xffffffffu, s, 4);
        s += __shfl_xor_sync(0xffffffffu, s, 8);
        s *= 0.125f;                                   // 1/sqrt(64)
        const float nm = fmaxf(m, s);
        const float f  = __expf(m - nm);
        const float p  = __expf(s - nm);
        acc.x = acc.x*f + p*v4.x;
        acc.y = acc.y*f + p*v4.y;
        acc.z = acc.z*f + p*v4.z;
        acc.w = acc.w*f + p*v4.w;
        l = l*f + p;
        m = nm;
    }

    // Merge the two half-warp streams (even keys / odd keys).
    const float mo = __shfl_xor_sync(0xffffffffu, m, 16);
    const float lo = __shfl_xor_sync(0xffffffffu, l, 16);
    float4 ao;
    ao.x = __shfl_xor_sync(0xffffffffu, acc.x, 16);
    ao.y = __shfl_xor_sync(0xffffffffu, acc.y, 16);
    ao.z = __shfl_xor_sync(0xffffffffu, acc.z, 16);
    ao.w = __shfl_xor_sync(0xffffffffu, acc.w, 16);
    const float M  = fmaxf(m, mo);
    const float wa = __expf(m - M), wb = __expf(mo - M);
    float4 comb;
    comb.x = acc.x*wa + ao.x*wb;
    comb.y = acc.y*wa + ao.y*wb;
    comb.z = acc.z*wa + ao.z*wb;
    comb.w = acc.w*wa + ao.w*wb;
    const float L = l*wa + lo*wb;

    if (lane < 16) ((float4*)sm_acc[warp])[l16] = comb;
    if (lane == 0) { sm_m[warp] = M; sm_l[warp] = L; }
    __syncthreads();

    // First 64 threads combine the 8 warp partials -> one block partial.
    if (threadIdx.x < NHD) {
        const int d = threadIdx.x;
        float Mb = sm_m[0];
#pragma unroll
        for (int w = 1; w < WARPS_PB; ++w) Mb = fmaxf(Mb, sm_m[w]);
        float Lb = 0.f, a = 0.f;
#pragma unroll
        for (int w = 0; w < WARPS_PB; ++w) {
            const float wg = __expf(sm_m[w] - Mb);
            a  += sm_acc[w][d] * wg;
            Lb += sm_l[w] * wg;
        }
        const int idx = bh*NCHUNK + blockIdx.x;
        g_acc[idx*NHD + d] = a;
        if (d == 0) { g_m[idx] = Mb; g_l[idx] = Lb; }
    }
}

// ---------------------------------------------------------------------------
// Kernel C: combine 32 block partials per (b,h) + fold in the new key/value
// (RoPE(k_new) fused).  grid NBH, 256 thr: c = tid>>6 handles chunks c,c+4,...
// ---------------------------------------------------------------------------
__global__ void attn_reduce() {
    const int bh  = blockIdx.x;
    const int tid = threadIdx.x;
    const int c = tid >> 6, d = tid & 63;
    const int b = bh >> 4, h = bh & 15;

    __shared__ float qs[NHD], ks[NHD];
    __shared__ float s_acc[4][NHD];
    __shared__ float s_l[4];
    __shared__ float red[NHD];
    __shared__ float s_dot;

    if (tid < 32) {
        const int i = tid;
        const float inv = expf(-((float)(2*i) / (float)NHD) * LN10000);
        float sn, cs; sincosf((float)NPAST * inv, &sn, &cs);
        const float* gq = g_qkv + b*ND + h*NHD;
        const float* gk = g_qkv + NB*ND + b*ND + h*NHD;
        const float q1 = gq[i], q2 = gq[i+32];
        qs[i]    = q1*cs - q2*sn;
        qs[i+32] = q2*cs + q1*sn;
        const float k1 = gk[i], k2 = gk[i+32];
        ks[i]    = k1*cs - k2*sn;
        ks[i+32] = k2*cs + k1*sn;
    }
    __syncthreads();

    const float* mptr = g_m + bh*NCHUNK;
    const float* lptr = g_l + bh*NCHUNK;
    const float* aptr = g_acc + (size_t)bh*NCHUNK*NHD;

    float M = -1e30f;
#pragma unroll
    for (int i = 0; i < NCHUNK; ++i) M = fmaxf(M, mptr[i]);

    float L = 0.f, a = 0.f;
#pragma unroll
    for (int i = c; i < NCHUNK; i += 4) {
        const float w = __expf(mptr[i] - M);
        L += lptr[i] * w;
        a += aptr[i*NHD + d] * w;
    }
    s_acc[c][d] = a;
    if (d == 0) s_l[c] = L;

    if (tid < NHD) red[tid] = qs[tid] * ks[tid];
    __syncthreads();

    if (tid < 32) {
        float v = red[tid] + red[tid + 32];
#pragma unroll
        for (int o = 16; o; o >>= 1) v += __shfl_xor_sync(0xffffffffu, v, o);
        if (tid == 0) s_dot = v * 0.125f;          // score of the new key
    }
    __syncthreads();

    if (tid < NHD) {
        float A  = s_acc[0][d] + s_acc[1][d] + s_acc[2][d] + s_acc[3][d];
        float Lt = s_l[0] + s_l[1] + s_l[2] + s_l[3];
        const float s_new = s_dot;
        const float M2 = fmaxf(M, s_new);
        const float w0 = __expf(M - M2);
        const float p  = __expf(s_new - M2);
        const float vd = g_qkv[2*NB*ND + b*ND + h*NHD + d];
        A  = A*w0 + p*vd;
        Lt = Lt*w0 + p;
        g_ctx[b*ND + h*NHD + d] = A / Lt;
    }
}

// ---------------------------------------------------------------------------
// Kernel D: output projection, batch-amortized.  grid 128, 256 thr.
// All 8 ctx vectors staged in smem; each Wo row read once, 8 accumulators.
// ---------------------------------------------------------------------------
__global__ void outproj_kernel(const float* __restrict__ Wo,
                               const float* __restrict__ bo,
                               float* __restrict__ out) {
    __shared__ float cs[NB*ND];                     // 32 KB
    for (int i = threadIdx.x; i < NB*ND; i += blockDim.x) cs[i] = g_ctx[i];
    __syncthreads();

    const int warp = threadIdx.x >> 5, lane = threadIdx.x & 31;
    const int r = blockIdx.x * 8 + warp;            // 0..1023
    const float4* Wr  = (const float4*)(Wo + (size_t)r * ND);
    const float4* cs4 = (const float4*)cs;
    float acc[NB];
#pragma unroll
    for (int b = 0; b < NB; ++b) acc[b] = 0.f;

#pragma unroll
    for (int it = 0; it < ND/128; ++it) {
        const float4 w4 = Wr[it*32 + lane];
#pragma unroll
        for (int b = 0; b < NB; ++b) {
            const float4 c4 = cs4[b*(ND/4) + it*32 + lane];
            acc[b] += w4.x*c4.x + w4.y*c4.y + w4.z*c4.z + w4.w*c4.w;
        }
    }
#pragma unroll
    for (int b = 0; b < NB; ++b) {
#pragma unroll
        for (int o = 16; o; o >>= 1) acc[b] += __shfl_xor_sync(0xffffffffu, acc[b], o);
    }
    if (lane == 0) {
        const float bo_ = bo[r];
#pragma unroll
        for (int b = 0; b < NB; ++b) out[b*ND + r] = acc[b] + bo_;
    }
}

// ---------------------------------------------------------------------------
extern "C" void kernel_launch(void* const* d_in, const int* in_sizes, int n_in,
                              void* d_out, int out_size) {
    const float* x      = (const float*)d_in[0];
    const float* Wq     = (const float*)d_in[1];
    const float* bq     = (const float*)d_in[2];
    const float* Wk     = (const float*)d_in[3];
    const float* bk     = (const float*)d_in[4];
    const float* Wv     = (const float*)d_in[5];
    const float* bv     = (const float*)d_in[6];
    const float* Wo     = (const float*)d_in[7];
    const float* bo     = (const float*)d_in[8];
    const float* past_k = (const float*)d_in[9];
    const float* past_v = (const float*)d_in[10];
    float* out = (float*)d_out;

    proj_kernel<<<3*ND/8, 256>>>(x, Wq, bq, Wk, bk, Wv, bv);
    attn_partial<<<dim3(NCHUNK, NBH), 256>>>(past_k, past_v);
    attn_reduce<<<NBH, 256>>>();
    outproj_kernel<<<ND/8, 256>>>(Wo, bo, out);
}